// round 7
// baseline (speedup 1.0000x reference)
#include <cuda_runtime.h>
#include <math.h>

// PolicyNetwork3x3: batch-1 fused conv(1->16,k2) + fc(64->32) + policy head
// (32->16->9, masked softmax) + value head (32->8->1, tanh).
// Entire network in ONE warp, one launch. Latency-bound by design.

__global__ void __launch_bounds__(32, 1)
policy3x3_kernel(const float* __restrict__ x,        // [9]   board 3x3
                 const float* __restrict__ conv_w,   // [16,1,2,2] = 64
                 const float* __restrict__ fc_w,     // [32,64] = 2048
                 const float* __restrict__ fc_b,     // [32]
                 const float* __restrict__ a1_w,     // [16,32] = 512
                 const float* __restrict__ a1_b,     // [16]
                 const float* __restrict__ a2_w,     // [9,16] = 144
                 const float* __restrict__ a2_b,     // [9]
                 const float* __restrict__ v1_w,     // [8,32] = 256
                 const float* __restrict__ v1_b,     // [8]
                 const float* __restrict__ v2_w,     // [8]
                 const float* __restrict__ v2_b,     // [1]
                 float* __restrict__ out)            // [10] = 9 probs + value
{
    const int t = threadIdx.x;  // 0..31, single warp

    __shared__ __align__(16) float sx[12];   // board (9 used)
    __shared__ __align__(16) float sy[64];   // conv+relu, channel-major flat
    __shared__ __align__(16) float sh[32];   // fc hidden
    __shared__ __align__(16) float sa[16];   // policy hidden
    __shared__ __align__(16) float sv[8];    // value hidden

    if (t < 9) sx[t] = x[t];
    __syncwarp();

    // ---- conv 1->16, k=2, valid: out[c, i, j], flat index o = c*4 + i*2 + j
    #pragma unroll
    for (int o = t; o < 64; o += 32) {
        const int c = o >> 2;
        const int p = o & 3;
        const int i = p >> 1;
        const int j = p & 1;
        const float* w = conv_w + c * 4;
        float s = sx[i * 3 + j]       * w[0]
                + sx[i * 3 + j + 1]   * w[1]
                + sx[(i + 1) * 3 + j] * w[2]
                + sx[(i + 1) * 3 + j + 1] * w[3];
        sy[o] = fmaxf(s, 0.0f);
    }
    __syncwarp();

    // ---- fc 64->32 + relu: thread t owns output row t
    {
        const float4* w4 = reinterpret_cast<const float4*>(fc_w + t * 64);
        float s = fc_b[t];
        #pragma unroll
        for (int k = 0; k < 16; k++) {
            const float4 w = w4[k];
            const float4 y = reinterpret_cast<const float4*>(sy)[k];
            s += w.x * y.x + w.y * y.y + w.z * y.z + w.w * y.w;
        }
        sh[t] = fmaxf(s, 0.0f);
    }
    __syncwarp();

    // ---- concurrent: lanes 0..15 -> a1 (32->16), lanes 16..23 -> v1 (32->8)
    if (t < 16) {
        const float4* w4 = reinterpret_cast<const float4*>(a1_w + t * 32);
        float s = a1_b[t];
        #pragma unroll
        for (int k = 0; k < 8; k++) {
            const float4 w = w4[k];
            const float4 h = reinterpret_cast<const float4*>(sh)[k];
            s += w.x * h.x + w.y * h.y + w.z * h.z + w.w * h.w;
        }
        sa[t] = fmaxf(s, 0.0f);
    } else if (t < 24) {
        const int r = t - 16;
        const float4* w4 = reinterpret_cast<const float4*>(v1_w + r * 32);
        float s = v1_b[r];
        #pragma unroll
        for (int k = 0; k < 8; k++) {
            const float4 w = w4[k];
            const float4 h = reinterpret_cast<const float4*>(sh)[k];
            s += w.x * h.x + w.y * h.y + w.z * h.z + w.w * h.w;
        }
        sv[r] = fmaxf(s, 0.0f);
    }
    __syncwarp();

    // ---- lanes 0..8: action logits (16->9); lane 16: v2 + tanh
    float logit = -INFINITY;
    if (t < 9) {
        const float4* w4 = reinterpret_cast<const float4*>(a2_w + t * 16);
        float s = a2_b[t];
        #pragma unroll
        for (int k = 0; k < 4; k++) {
            const float4 w = w4[k];
            const float4 a = reinterpret_cast<const float4*>(sa)[k];
            s += w.x * a.x + w.y * a.y + w.z * a.z + w.w * a.w;
        }
        logit = s;
    }
    if (t == 16) {
        float s = v2_b[0];
        #pragma unroll
        for (int k = 0; k < 8; k++) s += sv[k] * v2_w[k];
        out[9] = tanhf(s);
    }

    // ---- global max over logits (reference: jnp.max over all 9, unmasked)
    float m = logit;
    #pragma unroll
    for (int off = 16; off; off >>= 1)
        m = fmaxf(m, __shfl_xor_sync(0xffffffff, m, off));

    // ---- masked exp: cell legal iff |x| != 1
    float e = 0.0f;
    if (t < 9) {
        const float avail = (fabsf(sx[t]) != 1.0f) ? 1.0f : 0.0f;
        e = avail * expf(logit - m);
    }
    float sum = e;
    #pragma unroll
    for (int off = 16; off; off >>= 1)
        sum += __shfl_xor_sync(0xffffffff, sum, off);

    if (t < 9) out[t] = e / sum;
}

extern "C" void kernel_launch(void* const* d_in, const int* in_sizes, int n_in,
                              void* d_out, int out_size) {
    const float* x      = (const float*)d_in[0];
    const float* conv_w = (const float*)d_in[1];
    const float* fc_w   = (const float*)d_in[2];
    const float* fc_b   = (const float*)d_in[3];
    const float* a1_w   = (const float*)d_in[4];
    const float* a1_b   = (const float*)d_in[5];
    const float* a2_w   = (const float*)d_in[6];
    const float* a2_b   = (const float*)d_in[7];
    const float* v1_w   = (const float*)d_in[8];
    const float* v1_b   = (const float*)d_in[9];
    const float* v2_w   = (const float*)d_in[10];
    const float* v2_b   = (const float*)d_in[11];
    float* out = (float*)d_out;

    policy3x3_kernel<<<1, 32>>>(x, conv_w, fc_w, fc_b, a1_w, a1_b,
                                a2_w, a2_b, v1_w, v1_b, v2_w, v2_b, out);
}